// round 4
// baseline (speedup 1.0000x reference)
#include <cuda_runtime.h>

// Problem constants (fixed by setup_inputs)
#define BB    16
#define CIN   64
#define COUT  64
#define HH    224
#define WW    224
#define PHH   32
#define PWW   32
#define PLANE   (HH * WW)
#define PLANE4  (PLANE / 4)      // 12544 float4s per plane
#define W4      (WW / 4)         // 56
#define CLEAN4  ((HH - PHH) * W4)   // 10752
#define PATCH4  (PHH * W4)          // 1792

// Conv tiling: one CTA = (batch, 8-cout tile), full 32x32 patch.
// Thread = 2x2 pixel block x 8 cout -> 32 accumulators.
#define CIN_T 8
#define CO_T  8
#define CONV_BLOCKS (BB * (COUT / CO_T))   // 128
#define COPY_BLOCKS (BB * COUT)            // 1024
#define NTHREADS 256

#define S_R 36                    // padded row stride (floats)
#define S_C (34 * S_R)            // 1224 floats per cin plane (34 rows)

__global__ __launch_bounds__(NTHREADS, 4)
void inc_conv_fused_kernel(const float* __restrict__ in,      // (B,Cin,H,W)
                           const float* __restrict__ wgt,     // (Cout,Cin,3,3)
                           const float* __restrict__ bias,    // (Cout)
                           const float* __restrict__ src_out, // (B,Cout,H,W)
                           const int*   __restrict__ locs,    // (B,2) [y,x]
                           float*       __restrict__ dst)     // (B,Cout,H,W)
{
    const int tid = threadIdx.x;

    if (blockIdx.x >= CONV_BLOCKS) {
        // ------------------- COPY ROLE: one (b,c) plane per CTA -------------------
        const int plane = blockIdx.x - CONV_BLOCKS;   // b*64 + c
        const int b     = plane >> 6;
        const int py    = __ldg(&locs[2 * b]);
        const int px    = __ldg(&locs[2 * b + 1]);

        const float4* __restrict__ s4 = (const float4*)src_out + (size_t)plane * PLANE4;
        float4*       __restrict__ d4 = (float4*)dst          + (size_t)plane * PLANE4;

        const int split = py * W4;

        int i = tid;
        #pragma unroll 1
        for (; i + 7 * NTHREADS < CLEAN4; i += 8 * NTHREADS) {
            int k[8];
            #pragma unroll
            for (int u = 0; u < 8; ++u) {
                const int ii = i + u * NTHREADS;
                k[u] = ii < split ? ii : ii + PATCH4;
            }
            float4 v[8];
            #pragma unroll
            for (int u = 0; u < 8; ++u) v[u] = __ldcs(s4 + k[u]);
            #pragma unroll
            for (int u = 0; u < 8; ++u) __stcs(d4 + k[u], v[u]);
        }
        for (; i < CLEAN4; i += NTHREADS) {
            const int k = i < split ? i : i + PATCH4;
            __stcs(d4 + k, __ldcs(s4 + k));
        }

        // patch rows: mask patch columns
        #pragma unroll 1
        for (int t = tid; t < PATCH4; t += NTHREADS) {
            const int j  = t % W4;
            const int w0 = j * 4;
            const int k  = split + t;
            const bool overlap = (w0 + 3 >= px) && (w0 <= px + PWW - 1);
            if (!overlap) {
                __stcs(d4 + k, __ldcs(s4 + k));
            } else {
                const bool covered = (w0 >= px) && (w0 + 3 <= px + PWW - 1);
                if (!covered) {
                    const float4 v = __ldcs(s4 + k);
                    float* d = (float*)(d4 + k);
                    const float* sv = (const float*)&v;
                    #pragma unroll
                    for (int jj = 0; jj < 4; ++jj) {
                        const unsigned dw = (unsigned)(w0 + jj - px);
                        if (dw >= PWW) d[jj] = sv[jj];
                    }
                }
            }
        }
        return;
    }

    // ------------------- CONV ROLE -------------------
    __shared__ float s_in[CIN_T * S_C];          // 8*1224*4 = 39168 B
    __shared__ float s_w[CIN_T * 9 * CO_T];      // 576*4    =  2304 B

    const int b   = blockIdx.x >> 3;
    const int co0 = (blockIdx.x & 7) * CO_T;

    const int y = locs[2 * b];
    const int x = locs[2 * b + 1];

    const int tx = tid & 15;       // col-pair: output cols 2tx, 2tx+1
    const int ty = tid >> 4;       // row-pair: output rows 2ty, 2ty+1

    float acc[32];
    #pragma unroll
    for (int c = 0; c < 32; ++c) acc[c] = 0.0f;

    const int gr0 = y - 1;         // input tile origin (unpadded coords)
    const int gc0 = x - 1;

    for (int ci0 = 0; ci0 < CIN; ci0 += CIN_T) {
        // load input chunk: CIN_T x 34 x 34
        #pragma unroll 1
        for (int t = tid; t < CIN_T * 34 * 34; t += NTHREADS) {
            const int ci  = t / (34 * 34);
            const int rem = t - ci * (34 * 34);
            const int r   = rem / 34;
            const int c   = rem - r * 34;
            const int gr  = gr0 + r;
            const int gc  = gc0 + c;
            float v = 0.0f;
            if (gr >= 0 && gc >= 0)   // high side provably in-bounds
                v = in[((size_t)(b * CIN + ci0 + ci) * HH + gr) * WW + gc];
            s_in[ci * S_C + r * S_R + c] = v;
        }
        // weights transposed: s_w[(ci*9+k)*CO_T + co]
        for (int t = tid; t < CO_T * CIN_T * 9; t += NTHREADS) {
            const int co = t / (CIN_T * 9);
            const int r2 = t - co * (CIN_T * 9);
            const int ci = r2 / 9;
            const int k  = r2 - ci * 9;
            s_w[(ci * 9 + k) * CO_T + co] =
                wgt[((co0 + co) * CIN + ci0 + ci) * 9 + k];
        }
        __syncthreads();

        #pragma unroll 1
        for (int ci = 0; ci < CIN_T; ++ci) {
            const float* base = &s_in[ci * S_C + (2 * ty) * S_R + 2 * tx];
            float iv[4][4];
            #pragma unroll
            for (int r = 0; r < 4; ++r) {
                const float2 a = *(const float2*)(base + r * S_R);
                const float2 c2 = *(const float2*)(base + r * S_R + 2);
                iv[r][0] = a.x; iv[r][1] = a.y; iv[r][2] = c2.x; iv[r][3] = c2.y;
            }
            #pragma unroll
            for (int kh = 0; kh < 3; ++kh) {
                #pragma unroll
                for (int kw = 0; kw < 3; ++kw) {
                    const float4* wp = (const float4*)&s_w[(ci * 9 + kh * 3 + kw) * CO_T];
                    const float4 w0 = wp[0], w1 = wp[1];
                    #pragma unroll
                    for (int dy = 0; dy < 2; ++dy) {
                        #pragma unroll
                        for (int dx = 0; dx < 2; ++dx) {
                            const float v = iv[kh + dy][kw + dx];
                            float* a = &acc[(dy * 2 + dx) * 8];
                            a[0] += v * w0.x;  a[1] += v * w0.y;
                            a[2] += v * w0.z;  a[3] += v * w0.w;
                            a[4] += v * w1.x;  a[5] += v * w1.y;
                            a[6] += v * w1.z;  a[7] += v * w1.w;
                        }
                    }
                }
            }
        }
        __syncthreads();
    }

    // store: 4 pixels x 8 cout (+bias)
    #pragma unroll
    for (int co = 0; co < CO_T; ++co) {
        const float bv = bias[co0 + co];
        const size_t pbase = (size_t)(b * COUT + co0 + co) * PLANE;
        #pragma unroll
        for (int dy = 0; dy < 2; ++dy) {
            const int oy = y + 2 * ty + dy;
            #pragma unroll
            for (int dx = 0; dx < 2; ++dx) {
                const int ox = x + 2 * tx + dx;
                dst[pbase + (size_t)oy * WW + ox] = acc[(dy * 2 + dx) * 8 + co] + bv;
            }
        }
    }
}

extern "C" void kernel_launch(void* const* d_in, const int* in_sizes, int n_in,
                              void* d_out, int out_size) {
    const float* in_tensor  = (const float*)d_in[0];
    const float* weights    = (const float*)d_in[1];
    const float* biases     = (const float*)d_in[2];
    const float* out_stale  = (const float*)d_in[3];
    const int*   locs       = (const int*)d_in[4];
    float*       out        = (float*)d_out;

    inc_conv_fused_kernel<<<CONV_BLOCKS + COPY_BLOCKS, NTHREADS>>>(
        in_tensor, weights, biases, out_stale, locs, out);
}

// round 5
// speedup vs baseline: 1.6756x; 1.6756x over previous
#include <cuda_runtime.h>

// Problem constants (fixed by setup_inputs)
#define BB    16
#define CIN   64
#define COUT  64
#define HH    224
#define WW    224
#define PHH   32
#define PWW   32
#define PLANE   (HH * WW)
#define PLANE4  (PLANE / 4)      // 12544 float4s per plane
#define W4      (WW / 4)         // 56

// Conv tiling (R2 proven config)
#define CIN_T 16
#define CO_T  16
#define OH_T  8
#define CONV_BLOCKS (BB * (COUT / CO_T) * (PHH / OH_T))  // 256
#define HALVES 2
#define HALF_ROWS (HH / HALVES)                          // 112
#define COPY_BLOCKS (BB * COUT * HALVES)                 // 2048
#define NTHREADS 256

#define SIN_STRIDE_R 36
#define SIN_STRIDE_C (10 * SIN_STRIDE_R)

__global__ __launch_bounds__(NTHREADS, 4)
void inc_conv_fused_kernel(const float* __restrict__ in,      // (B,Cin,H,W)
                           const float* __restrict__ wgt,     // (Cout,Cin,3,3)
                           const float* __restrict__ bias,    // (Cout)
                           const float* __restrict__ src_out, // (B,Cout,H,W)
                           const int*   __restrict__ locs,    // (B,2) [y,x]
                           float*       __restrict__ dst)     // (B,Cout,H,W)
{
    const int tid = threadIdx.x;

    if (blockIdx.x >= CONV_BLOCKS) {
        // ------------- COPY ROLE: one half-plane (112 rows) per CTA -------------
        const int id    = blockIdx.x - CONV_BLOCKS;   // plane*2 + half
        const int plane = id >> 1;                    // b*64 + c
        const int half  = id & 1;
        const int b     = plane >> 6;
        const int py    = __ldg(&locs[2 * b]);
        const int px    = __ldg(&locs[2 * b + 1]);

        const float4* __restrict__ s4 = (const float4*)src_out + (size_t)plane * PLANE4;
        float4*       __restrict__ d4 = (float4*)dst          + (size_t)plane * PLANE4;

        const int r0 = half * HALF_ROWS;
        const int r1 = r0 + HALF_ROWS;
        // patch-row intersection with [r0, r1)
        const int pr0 = max(py, r0);
        const int pr1 = min(py + PHH, r1);
        const int np  = max(0, pr1 - pr0);            // patch rows in this half
        const int clean  = (HALF_ROWS - np) * W4;     // clean float4s in this half
        const int splitl = (np > 0 ? (pr0 - r0) : HALF_ROWS) * W4;
        const int skip   = np * W4;
        const int base   = r0 * W4;

        // --- clean float4s, software-pipelined (8 loads in flight) ---
        int i = tid;
        if (i + 3 * NTHREADS < clean) {
            int k[4]; float4 v[4];
            #pragma unroll
            for (int u = 0; u < 4; ++u) {
                const int ii = i + u * NTHREADS;
                k[u] = base + (ii < splitl ? ii : ii + skip);
            }
            #pragma unroll
            for (int u = 0; u < 4; ++u) v[u] = __ldcs(s4 + k[u]);

            for (i += 4 * NTHREADS; i + 3 * NTHREADS < clean; i += 4 * NTHREADS) {
                int kn[4]; float4 vn[4];
                #pragma unroll
                for (int u = 0; u < 4; ++u) {
                    const int ii = i + u * NTHREADS;
                    kn[u] = base + (ii < splitl ? ii : ii + skip);
                }
                #pragma unroll
                for (int u = 0; u < 4; ++u) vn[u] = __ldcs(s4 + kn[u]);   // next loads first
                #pragma unroll
                for (int u = 0; u < 4; ++u) __stcs(d4 + k[u], v[u]);      // then current stores
                #pragma unroll
                for (int u = 0; u < 4; ++u) { k[u] = kn[u]; v[u] = vn[u]; }
            }
            #pragma unroll
            for (int u = 0; u < 4; ++u) __stcs(d4 + k[u], v[u]);
        }
        for (; i < clean; i += NTHREADS) {
            const int k = base + (i < splitl ? i : i + skip);
            __stcs(d4 + k, __ldcs(s4 + k));
        }

        // --- patch rows in this half: mask patch columns ---
        const int pbase = pr0 * W4;
        #pragma unroll 1
        for (int t = tid; t < skip; t += NTHREADS) {
            const int j  = t % W4;
            const int w0 = j * 4;
            const int k  = pbase + t;
            const bool overlap = (w0 + 3 >= px) && (w0 <= px + PWW - 1);
            if (!overlap) {
                __stcs(d4 + k, __ldcs(s4 + k));
            } else {
                const bool covered = (w0 >= px) && (w0 + 3 <= px + PWW - 1);
                if (!covered) {
                    const float4 v = __ldcs(s4 + k);
                    float* d = (float*)(d4 + k);
                    const float* sv = (const float*)&v;
                    #pragma unroll
                    for (int jj = 0; jj < 4; ++jj) {
                        const unsigned dw = (unsigned)(w0 + jj - px);
                        if (dw >= PWW) d[jj] = sv[jj];
                    }
                }
            }
        }
        return;
    }

    // ------------------- CONV ROLE (R2 proven config) -------------------
    __shared__ float s_in[CIN_T * SIN_STRIDE_C];
    __shared__ float s_w[CIN_T * 9 * CO_T];

    const int conv_id = blockIdx.x;
    const int b       = conv_id >> 4;
    const int rem     = conv_id & 15;
    const int co0     = (rem >> 2) * CO_T;
    const int oh0     = (rem & 3) * OH_T;

    const int y = locs[2 * b];
    const int x = locs[2 * b + 1];

    const int oh_l = tid >> 5;
    const int ow   = tid & 31;

    float acc[CO_T];
    #pragma unroll
    for (int c = 0; c < CO_T; ++c) acc[c] = 0.0f;

    const int gr0 = y + oh0 - 1;
    const int gc0 = x - 1;

    for (int ci0 = 0; ci0 < CIN; ci0 += CIN_T) {
        for (int t = tid; t < CIN_T * 10 * 34; t += NTHREADS) {
            const int ci = t / (10 * 34);
            const int r  = (t / 34) % 10;
            const int c  = t % 34;
            const int gr = gr0 + r;
            const int gc = gc0 + c;
            float v = 0.0f;
            if (gr >= 0 && gc >= 0)
                v = in[((size_t)(b * CIN + ci0 + ci) * HH + gr) * WW + gc];
            s_in[ci * SIN_STRIDE_C + r * SIN_STRIDE_R + c] = v;
        }
        for (int t = tid; t < CO_T * CIN_T * 9; t += NTHREADS) {
            const int co = t / (CIN_T * 9);
            const int r2 = t % (CIN_T * 9);
            const int ci = r2 / 9;
            const int k  = r2 % 9;
            s_w[(ci * 9 + k) * CO_T + co] =
                wgt[((co0 + co) * CIN + ci0 + ci) * 9 + k];
        }
        __syncthreads();

        #pragma unroll 4
        for (int ci = 0; ci < CIN_T; ++ci) {
            const float* ibase = &s_in[ci * SIN_STRIDE_C + oh_l * SIN_STRIDE_R + ow];
            #pragma unroll
            for (int kh = 0; kh < 3; ++kh) {
                const float i0 = ibase[kh * SIN_STRIDE_R + 0];
                const float i1 = ibase[kh * SIN_STRIDE_R + 1];
                const float i2 = ibase[kh * SIN_STRIDE_R + 2];
                #pragma unroll
                for (int kw = 0; kw < 3; ++kw) {
                    const float iv = (kw == 0) ? i0 : ((kw == 1) ? i1 : i2);
                    const float4* wp =
                        (const float4*)&s_w[(ci * 9 + kh * 3 + kw) * CO_T];
                    const float4 w0 = wp[0], w1 = wp[1], w2 = wp[2], w3 = wp[3];
                    acc[0]  += iv * w0.x;  acc[1]  += iv * w0.y;
                    acc[2]  += iv * w0.z;  acc[3]  += iv * w0.w;
                    acc[4]  += iv * w1.x;  acc[5]  += iv * w1.y;
                    acc[6]  += iv * w1.z;  acc[7]  += iv * w1.w;
                    acc[8]  += iv * w2.x;  acc[9]  += iv * w2.y;
                    acc[10] += iv * w2.z;  acc[11] += iv * w2.w;
                    acc[12] += iv * w3.x;  acc[13] += iv * w3.y;
                    acc[14] += iv * w3.z;  acc[15] += iv * w3.w;
                }
            }
        }
        __syncthreads();
    }

    const int oy = y + oh0 + oh_l;
    const int ox = x + ow;
    #pragma unroll
    for (int c = 0; c < CO_T; ++c) {
        dst[((size_t)(b * COUT + co0 + c) * HH + oy) * WW + ox] =
            acc[c] + bias[co0 + c];
    }
}

extern "C" void kernel_launch(void* const* d_in, const int* in_sizes, int n_in,
                              void* d_out, int out_size) {
    const float* in_tensor  = (const float*)d_in[0];
    const float* weights    = (const float*)d_in[1];
    const float* biases     = (const float*)d_in[2];
    const float* out_stale  = (const float*)d_in[3];
    const int*   locs       = (const int*)d_in[4];
    float*       out        = (float*)d_out;

    inc_conv_fused_kernel<<<CONV_BLOCKS + COPY_BLOCKS, NTHREADS>>>(
        in_tensor, weights, biases, out_stale, locs, out);
}